// round 12
// baseline (speedup 1.0000x reference)
#include <cuda_runtime.h>
#include <cuda_fp16.h>
#include <cstdint>

// ---------------- problem constants ----------------
#define NIN   4096
#define NOUT  1024
#define BC    128          // B*C = 4*32
#define C_DIM 32

// GEMM: D[o(1024), bc(128)] = sum_k M[o,k] * gftT[bc,k]
// CTA tile: 128 o x 64 bc; grid = 8 (o) x 2 (bc) x 16 (K-split) = 256 CTAs
#define KSPLIT 16
#define KPB    (NIN / KSPLIT)   // 256
#define KC     64               // k per smem chunk
#define NCHUNK (KPB / KC)       // 4
#define ROWH   72               // smem row stride in halves (144B = 9x16B)
#define ATILEH (128 * ROWH)     // A tile halves
#define BTILEH (64  * ROWH)     // B tile halves
#define STAGEH (ATILEH + 2 * BTILEH)   // halves per stage

// zero coverage: M = 4M halves = 524288 uint4; out = 131072 f32 = 32768 uint4
#define ZVEC_M   524288
#define ZVEC_ALL (ZVEC_M + 32768)   // 557056 -> 2176 blocks x 256
#define XFORM_BLKS 256              // 4 b x 64 n-tiles of 64

// ---------------- device scratch ----------------
__device__ __align__(16) __half g_Mh[NOUT * NIN];  // 8.4 MB count matrix (fp16)
__device__ __align__(16) __half g_ghi[BC * NIN];   // 1 MB  (G@F)^T hi (fp16)
__device__ __align__(16) __half g_glo[BC * NIN];   // 1 MB  (G@F)^T lo (fp16)

__device__ __forceinline__ uint32_t smem_u32(const void* p) {
    uint32_t a;
    asm("{ .reg .u64 t; cvta.to.shared.u64 t, %1; cvt.u32.u64 %0, t; }" : "=r"(a) : "l"(p));
    return a;
}
__device__ __forceinline__ void cp16(uint32_t dst, const void* src) {
    asm volatile("cp.async.cg.shared.global [%0], [%1], 16;" :: "r"(dst), "l"(src));
}
__device__ __forceinline__ void cp_commit() {
    asm volatile("cp.async.commit_group;" ::: "memory");
}
__device__ __forceinline__ void cp_wait0() {
    asm volatile("cp.async.wait_group 0;" ::: "memory");
}
__device__ __forceinline__ void ldsm_x4(uint32_t* r, uint32_t addr) {
    asm volatile("ldmatrix.sync.aligned.m8n8.x4.shared.b16 {%0,%1,%2,%3}, [%4];"
                 : "=r"(r[0]), "=r"(r[1]), "=r"(r[2]), "=r"(r[3]) : "r"(addr));
}
__device__ __forceinline__ void mma16816(float* c, const uint32_t* a,
                                         uint32_t b0, uint32_t b1) {
    asm volatile(
        "mma.sync.aligned.m16n8k16.row.col.f32.f16.f16.f32 "
        "{%0,%1,%2,%3}, {%4,%5,%6,%7}, {%8,%9}, {%0,%1,%2,%3};"
        : "+f"(c[0]), "+f"(c[1]), "+f"(c[2]), "+f"(c[3])
        : "r"(a[0]), "r"(a[1]), "r"(a[2]), "r"(a[3]), "r"(b0), "r"(b1));
}

// pack 4 floats -> 4 halves (two half2) as uint2 for one 8B store
__device__ __forceinline__ uint2 pack_h4(float a, float b, float c, float d) {
    __half2 lo = __floats2half2_rn(a, b);
    __half2 hi = __floats2half2_rn(c, d);
    uint2 r;
    r.x = *reinterpret_cast<uint32_t*>(&lo);
    r.y = *reinterpret_cast<uint32_t*>(&hi);
    return r;
}

// ---------------------------------------------------------------------------
// Kernel 1: fused [zero M + zero out] and [channel-GEMM -> gftT hi/lo].
// Blocks 0..255: transform (4 b x 64 n-tiles). Thread = 2 oc x 4 n:
//   96 LDS (32x LDS.128 F + 64 broadcast G) per 256 FMA  (was ~512 LDS).
// Blocks 256..2431: zeroing (one uint4 per thread).
// ---------------------------------------------------------------------------
__global__ void qc_prep(const float* __restrict__ F, const float* __restrict__ G,
                        float* __restrict__ out) {
    __shared__ float4 Fs4[C_DIM * 16];   // [i][n4] 32 x 16 float4 = 64 n
    __shared__ float  Gs[C_DIM * 33];    // [oc][i], pad 33
    int t = threadIdx.x;

    if (blockIdx.x >= XFORM_BLKS) {
        int gt = (blockIdx.x - XFORM_BLKS) * 256 + t;
        uint4 z = make_uint4(0u, 0u, 0u, 0u);
        if (gt < ZVEC_M)
            reinterpret_cast<uint4*>(g_Mh)[gt] = z;
        else
            reinterpret_cast<uint4*>(out)[gt - ZVEC_M] = z;
        return;
    }

    int b  = blockIdx.x >> 6;          // 0..3
    int n0 = (blockIdx.x & 63) * 64;   // n tile start

    // Stage F tile 32 x 64 as float4 (512 vecs, 2 per thread, coalesced)
    #pragma unroll
    for (int j = 0; j < 2; j++) {
        int seg = t + j * 256;                   // 0..511
        int i   = seg >> 4, n4 = seg & 15;
        Fs4[i * 16 + n4] = *reinterpret_cast<const float4*>(
            &F[b * (C_DIM * NIN) + i * NIN + n0 + n4 * 4]);
    }
    // Stage G [oc][i] with pad-33 rows
    #pragma unroll
    for (int j = 0; j < 4; j++) {
        int idx = t + j * 256;
        Gs[(idx >> 5) * 33 + (idx & 31)] = G[idx];
    }
    __syncthreads();

    int n4  = t & 15;          // float4 column (n = n0 + n4*4 ..+3)
    int ocp = t >> 4;          // 0..15 -> oc pair (2*ocp, 2*ocp+1)
    int oc0 = ocp * 2;

    float4 a0 = make_float4(0.f, 0.f, 0.f, 0.f);
    float4 a1 = make_float4(0.f, 0.f, 0.f, 0.f);
    #pragma unroll
    for (int i = 0; i < 32; i++) {
        float4 f = Fs4[i * 16 + n4];
        float g0 = Gs[oc0 * 33 + i];
        float g1 = Gs[(oc0 + 1) * 33 + i];
        a0.x = fmaf(g0, f.x, a0.x); a0.y = fmaf(g0, f.y, a0.y);
        a0.z = fmaf(g0, f.z, a0.z); a0.w = fmaf(g0, f.w, a0.w);
        a1.x = fmaf(g1, f.x, a1.x); a1.y = fmaf(g1, f.y, a1.y);
        a1.z = fmaf(g1, f.z, a1.z); a1.w = fmaf(g1, f.w, a1.w);
    }

    // write hi/lo (4 halves = 8B per store)
    #pragma unroll
    for (int q = 0; q < 2; q++) {
        float4 s = q ? a1 : a0;
        int row = b * 32 + oc0 + q;
        long off = (long)row * NIN + n0 + n4 * 4;

        float hx = __half2float(__float2half_rn(s.x));
        float hy = __half2float(__float2half_rn(s.y));
        float hz = __half2float(__float2half_rn(s.z));
        float hw = __half2float(__float2half_rn(s.w));

        *reinterpret_cast<uint2*>(&g_ghi[off]) = pack_h4(s.x, s.y, s.z, s.w);
        *reinterpret_cast<uint2*>(&g_glo[off]) =
            pack_h4(s.x - hx, s.y - hy, s.z - hz, s.w - hw);
    }
}

// ---------------------------------------------------------------------------
// Kernel 2: build count matrix. 4 edges per thread (int4 index loads),
// spread fp16 atomics (RED.F16).
// ---------------------------------------------------------------------------
__global__ void qc_count(const int* __restrict__ idx_out,
                         const int* __restrict__ idx_in, int E) {
    int base = (blockIdx.x * blockDim.x + threadIdx.x) * 4;
    const __half one = __float2half(1.0f);
    if (base + 3 < E) {
        int4 io = *reinterpret_cast<const int4*>(idx_out + base);
        int4 ii = *reinterpret_cast<const int4*>(idx_in  + base);
        atomicAdd(&g_Mh[io.x * NIN + ii.x], one);
        atomicAdd(&g_Mh[io.y * NIN + ii.y], one);
        atomicAdd(&g_Mh[io.z * NIN + ii.z], one);
        atomicAdd(&g_Mh[io.w * NIN + ii.w], one);
    } else {
        for (int e = base; e < E; e++)
            atomicAdd(&g_Mh[idx_out[e] * NIN + idx_in[e]], one);
    }
}

// ---------------------------------------------------------------------------
// Kernel 3: HMMA GEMM, cp.async double-buffered, 2 CTAs/SM.
// CTA = 256 threads (8 warps, 4 o-groups x 2 bc-groups), tile 128o x 64bc.
// Epilogue RED-adds into out (bc-major, zeroed by qc_prep).
// ---------------------------------------------------------------------------
__global__ void __launch_bounds__(256, 2) qc_gemm_mma(float* __restrict__ out) {
    extern __shared__ __half sm[];
    int t    = threadIdx.x;
    int wid  = t >> 5;
    int lane = t & 31;
    int bid  = blockIdx.x;
    int mt_b = bid & 7;              // o tile
    int nb   = (bid >> 3) & 1;       // bc half
    int ks   = bid >> 4;             // K split
    int o0   = mt_b * 128;
    int bc0  = nb * 64;
    int k0   = ks * KPB;
    int wo   = (wid >> 1) * 32;      // warp o offset (0/32/64/96)
    int n0w  = (wid & 1) * 32;       // warp bc offset within CTA (0/32)

    uint32_t sbase = smem_u32(sm);
    uint32_t sA[2], sBh[2], sBl[2];
    #pragma unroll
    for (int s = 0; s < 2; s++) {
        sA[s]  = sbase + (s * STAGEH) * 2;
        sBh[s] = sA[s] + ATILEH * 2;
        sBl[s] = sBh[s] + BTILEH * 2;
    }

    // prefetch helper: A 1024 segs (4/thr), Bh/Bl 512 segs (2/thr) of 16B
    auto prefetch = [&](int stage, int kc) {
        #pragma unroll
        for (int j = 0; j < 4; j++) {
            int seg = t + j * 256;                 // 0..1023
            int row = seg >> 3, col = seg & 7;
            cp16(sA[stage] + row * 144 + col * 16,
                 &g_Mh[(o0 + row) * NIN + kc + col * 8]);
        }
        #pragma unroll
        for (int j = 0; j < 2; j++) {
            int seg = t + j * 256;                 // 0..511
            int row = seg >> 3, col = seg & 7;
            int off = row * 144 + col * 16;
            const int gr = (bc0 + row) * NIN + kc + col * 8;
            cp16(sBh[stage] + off, &g_ghi[gr]);
            cp16(sBl[stage] + off, &g_glo[gr]);
        }
        cp_commit();
    };

    prefetch(0, k0);

    float acc[2][4][4];
    #pragma unroll
    for (int i = 0; i < 2; i++)
        #pragma unroll
        for (int j = 0; j < 4; j++)
            #pragma unroll
            for (int q = 0; q < 4; q++) acc[i][j][q] = 0.f;

    for (int c = 0; c < NCHUNK; c++) {
        int buf = c & 1;
        cp_wait0();
        __syncthreads();

        if (c + 1 < NCHUNK) prefetch(buf ^ 1, k0 + (c + 1) * KC);

        #pragma unroll
        for (int kk = 0; kk < KC; kk += 16) {
            uint32_t a[2][4];
            #pragma unroll
            for (int mt = 0; mt < 2; mt++)
                ldsm_x4(a[mt], sA[buf] + 2 * ((wo + mt * 16 + (lane & 15)) * ROWH
                                              + kk + (lane >> 4) * 8));
            #pragma unroll
            for (int h = 0; h < 2; h++) {
                uint32_t sB = h ? sBl[buf] : sBh[buf];
                #pragma unroll
                for (int ng = 0; ng < 2; ng++) {
                    uint32_t b[4];
                    ldsm_x4(b, sB + 2 * ((n0w + ng * 16 + (lane & 15)) * ROWH
                                          + kk + (lane >> 4) * 8));
                    #pragma unroll
                    for (int mt = 0; mt < 2; mt++) {
                        mma16816(acc[mt][ng * 2 + 0], a[mt], b[0], b[2]);
                        mma16816(acc[mt][ng * 2 + 1], a[mt], b[1], b[3]);
                    }
                }
            }
        }
    }

    // Epilogue: RED into out[bc*NOUT + o]. Frag rows = lane>>2 (+8),
    // cols = (lane&3)*2 + {0,1}.
    #pragma unroll
    for (int mt = 0; mt < 2; mt++) {
        #pragma unroll
        for (int nt = 0; nt < 4; nt++) {
            int o  = o0 + wo + mt * 16 + (lane >> 2);
            int bc = bc0 + n0w + nt * 8 + (lane & 3) * 2;
            atomicAdd(&out[bc * NOUT + o],             acc[mt][nt][0]);
            atomicAdd(&out[(bc + 1) * NOUT + o],       acc[mt][nt][1]);
            atomicAdd(&out[bc * NOUT + o + 8],         acc[mt][nt][2]);
            atomicAdd(&out[(bc + 1) * NOUT + o + 8],   acc[mt][nt][3]);
        }
    }
}

// ---------------------------------------------------------------------------
extern "C" void kernel_launch(void* const* d_in, const int* in_sizes, int n_in,
                              void* d_out, int out_size) {
    const float* features = (const float*)d_in[0];   // (4,32,4096) f32
    const float* G        = (const float*)d_in[1];   // (32,32)     f32
    const int*   idx_out  = (const int*)d_in[2];     // (E,) i32
    const int*   idx_in   = (const int*)d_in[3];     // (E,) i32
    float*       out      = (float*)d_out;           // (4,32,1024) f32
    int E = in_sizes[2];

    static const int GEMM_SMEM = 2 * STAGEH * (int)sizeof(__half);  // 73728
    cudaFuncSetAttribute(qc_gemm_mma,
                         cudaFuncAttributeMaxDynamicSharedMemorySize, GEMM_SMEM);

    qc_prep<<<XFORM_BLKS + ZVEC_ALL / 256, 256>>>(features, G, out);
    int cthreads = (E + 3) / 4;
    qc_count<<<(cthreads + 255) / 256, 256>>>(idx_out, idx_in, E);
    qc_gemm_mma<<<8 * 2 * KSPLIT, 256, GEMM_SMEM>>>(out);
}